// round 8
// baseline (speedup 1.0000x reference)
#include <cuda_runtime.h>
#include <cstdint>
#include <cstddef>
#include <cstring>

#define NTIME 20
#define V     128
#define F     128
#define LRELU_ALPHA 0.2f
#define LOG2E 1.4426950408889634f

#define OUT_HP_ELEMS   (NTIME * V * F)
#define ATT_OFF        OUT_HP_ELEMS

__device__ float g_Wh[NTIME * V * F];
__device__ float g_e1[NTIME * V * F];   // scaled by LOG2E
__device__ float g_e2[NTIME * V * F];   // scaled by LOG2E

// ---- packed f32x2 helpers (Blackwell) --------------------------------------
__device__ __forceinline__ float2 addx2(float2 a, float2 b) {
    unsigned long long ua, ub, uc;
    memcpy(&ua, &a, 8); memcpy(&ub, &b, 8);
    asm("add.rn.f32x2 %0, %1, %2;" : "=l"(uc) : "l"(ua), "l"(ub));
    float2 c; memcpy(&c, &uc, 8); return c;
}
__device__ __forceinline__ float2 mulx2(float2 a, float2 b) {
    unsigned long long ua, ub, uc;
    memcpy(&ua, &a, 8); memcpy(&ub, &b, 8);
    asm("mul.rn.f32x2 %0, %1, %2;" : "=l"(uc) : "l"(ua), "l"(ub));
    float2 c; memcpy(&c, &uc, 8); return c;
}
__device__ __forceinline__ float ex2(float x) {
    float r; asm("ex2.approx.f32 %0, %1;" : "=f"(r) : "f"(x)); return r;
}

// ----------------------------------------------------------------------------
// Shared gemm core: dst[m0:m0+32] = src_tile(32xF in smem) @ M, optional scale.
// 512 threads: f = tid&127, q = tid>>7; thread computes 8 rows (q*8+r).
// W loads software-pipelined (double-buffered regs) and fully unrolled.
// ----------------------------------------------------------------------------
#define MT 32

__device__ __forceinline__ void gemm_core(
    const float* __restrict__ smtile,   // [MT][F]
    const float* __restrict__ M,        // [F][F]
    float* __restrict__ dst,            // row m0, stride F
    int m0, int f, int q, float scale)
{
    float acc[8] = {0.f,0.f,0.f,0.f,0.f,0.f,0.f,0.f};
    float mv[4], nv[4];

#pragma unroll
    for (int u = 0; u < 4; u++)
        mv[u] = __ldg(M + u * F + f);

#pragma unroll
    for (int k4 = 0; k4 < F / 4; k4++) {
        if (k4 < F / 4 - 1) {
#pragma unroll
            for (int u = 0; u < 4; u++)
                nv[u] = __ldg(M + ((k4 + 1) * 4 + u) * F + f);
        }
#pragma unroll
        for (int r = 0; r < 8; r++) {
            const float4 hv = ((const float4*)(smtile + (q * 8 + r) * F))[k4];
            acc[r] = fmaf(hv.x, mv[0], acc[r]);
            acc[r] = fmaf(hv.y, mv[1], acc[r]);
            acc[r] = fmaf(hv.z, mv[2], acc[r]);
            acc[r] = fmaf(hv.w, mv[3], acc[r]);
        }
#pragma unroll
        for (int u = 0; u < 4; u++) mv[u] = nv[u];
    }

#pragma unroll
    for (int r = 0; r < 8; r++)
        dst[(size_t)(m0 + q * 8 + r) * F + f] = acc[r] * scale;
}

// Kernel A: Wh = h @ W. grid = 80.
__global__ void __launch_bounds__(512) gemmA(
    const float* __restrict__ h, const float* __restrict__ W)
{
    __shared__ float hs[MT * F];
    const int tid = threadIdx.x;
    const int m0  = blockIdx.x * MT;

    // 32*128 floats = 1024 float4, 2 per thread
    ((float4*)hs)[tid]       = ((const float4*)(h + (size_t)m0 * F))[tid];
    ((float4*)hs)[tid + 512] = ((const float4*)(h + (size_t)m0 * F))[tid + 512];
    __syncthreads();

    gemm_core(hs, W, g_Wh, m0, tid & 127, tid >> 7, 1.0f);
}

// Kernel B: e{1,2} = (Wh @ a{1,2}) * LOG2E. grid = (80, 2).
__global__ void __launch_bounds__(512) gemmB(const float* __restrict__ a)
{
    __shared__ float ws[MT * F];
    const int tid = threadIdx.x;
    const int m0  = blockIdx.x * MT;
    const int by  = blockIdx.y;

    ((float4*)ws)[tid]       = ((const float4*)(g_Wh + (size_t)m0 * F))[tid];
    ((float4*)ws)[tid + 512] = ((const float4*)(g_Wh + (size_t)m0 * F))[tid + 512];
    __syncthreads();

    gemm_core(ws, a + (size_t)by * F * F, by ? g_e2 : g_e1,
              m0, tid & 127, tid >> 7, LOG2E);
}

// ----------------------------------------------------------------------------
// Kernel C: attention (unchanged from R7). j-split: two warps per (i, f-half),
// each owning 64 j's; partial (s,num) exchanged via smem; 10240 total warps.
// Block = 512 threads (8 i x 2 jh), grid = 32 x 20 = 640, smem 72KB, 3 CTA/SM.
// ----------------------------------------------------------------------------
#define FH  64
#define IPB 8
#define ATTN_SMEM_BYTES ((2 * V * FH + 16 * 32 * 4) * (int)sizeof(float))

__global__ void __launch_bounds__(512, 3) attn_fused(
    const float* __restrict__ adj,
    float* __restrict__ out)
{
    extern __shared__ float sm[];
    float*  e2s = sm;                        // [V][FH]  (scaled by LOG2E)
    float*  whs = sm + V * FH;               // [V][FH]
    float4* red = (float4*)(sm + 2 * V * FH);

    const int t    = blockIdx.y;
    const int bx   = blockIdx.x;      // 0..31
    const int fh   = bx & 1;
    const int ig   = bx >> 1;         // 0..15
    const int tid  = threadIdx.x;
    const int lane = tid & 31;
    const int w    = tid >> 5;        // warp 0..15
    const int il   = w >> 1;          // local i 0..7
    const int jh   = w & 1;           // j-half
    const int i    = ig * IPB + il;
    const int f2   = fh * FH + lane * 2;

    uint32_t bits[2];
    {
        const float* arow = adj + (size_t)i * V + jh * 64;
        bits[0] = __ballot_sync(0xFFFFFFFFu, arow[lane]      > 0.0f);
        bits[1] = __ballot_sync(0xFFFFFFFFu, arow[32 + lane] > 0.0f);
    }

    {
        const float* e2g = g_e2 + (size_t)t * V * F + fh * FH;
        const float* whg = g_Wh + (size_t)t * V * F + fh * FH;
#pragma unroll
        for (int u = 0; u < 4; u++) {
            const int idx = tid + u * 512;
            const int j = idx >> 4, c = idx & 15;
            ((float4*)e2s)[idx] = *(const float4*)(e2g + j * F + c * 4);
            ((float4*)whs)[idx] = *(const float4*)(whg + j * F + c * 4);
        }
    }

    const float2 e1v = *(const float2*)(g_e1 + ((size_t)t * V + i) * F + f2);
    const float2 A2  = make_float2(LRELU_ALPHA, LRELU_ALPHA);
    __syncthreads();

    const float* e2l = e2s + jh * 64 * FH + lane * 2;
    const float* whl = whs + jh * 64 * FH + lane * 2;

    float s0 = 0.0f, s1 = 0.0f, n0 = 0.0f, n1 = 0.0f;
#pragma unroll
    for (int ww = 0; ww < 2; ww++) {
        const uint32_t bw = bits[ww];
        const float* e2w = e2l + ww * 32 * FH;
        const float* whw = whl + ww * 32 * FH;
#pragma unroll
        for (int b = 0; b < 32; b++) {
            if (bw & (1u << b)) {
                const float2 e2v = *(const float2*)(e2w + b * FH);
                const float2 v   = addx2(e1v, e2v);
                const float2 av  = mulx2(v, A2);
                const float  m0v = fmaxf(v.x, av.x);
                const float  m1v = fmaxf(v.y, av.y);
                const float  p0  = ex2(m0v);
                const float  p1  = ex2(m1v);
                const float2 wv  = *(const float2*)(whw + b * FH);
                s0 += p0;  s1 += p1;
                n0 = fmaf(p0, wv.x, n0);
                n1 = fmaf(p1, wv.y, n1);
            }
        }
    }

    red[w * 32 + lane] = make_float4(s0, s1, n0, n1);
    __syncthreads();
    {
        const float4 o = red[(w ^ 1) * 32 + lane];
        s0 += o.x; s1 += o.y; n0 += o.z; n1 += o.w;
    }

    const float r0 = 1.0f / s0;
    const float r1 = 1.0f / s1;

    if (jh == 0) {
        const float hp0 = n0 * r0;
        const float hp1 = n1 * r1;
        float2 o;
        o.x = (hp0 > 0.0f) ? hp0 : expm1f(hp0);
        o.y = (hp1 > 0.0f) ? hp1 : expm1f(hp1);
        *(float2*)(out + ((size_t)t * V + i) * F + f2) = o;
    }

    float* ab = out + ATT_OFF + (((size_t)t * V + i) * V + jh * 64) * F + f2;
#pragma unroll
    for (int ww = 0; ww < 2; ww++) {
        const uint32_t bw = bits[ww];
        const float* e2w = e2l + ww * 32 * FH;
        float* abw = ab + (size_t)ww * 32 * F;
#pragma unroll
        for (int b = 0; b < 32; b++) {
            float2 pv;
            if (bw & (1u << b)) {
                const float2 e2v = *(const float2*)(e2w + b * FH);
                const float2 v   = addx2(e1v, e2v);
                const float2 av  = mulx2(v, A2);
                const float  m0v = fmaxf(v.x, av.x);
                const float  m1v = fmaxf(v.y, av.y);
                pv.x = ex2(m0v) * r0;
                pv.y = ex2(m1v) * r1;
            } else {
                pv.x = 0.0f; pv.y = 0.0f;
            }
            __stcs((float2*)(abw + b * F), pv);
        }
    }
}

// ----------------------------------------------------------------------------
extern "C" void kernel_launch(void* const* d_in, const int* in_sizes, int n_in,
                              void* d_out, int out_size)
{
    const float* h   = (const float*)d_in[0];   // [2560,128]
    const float* adj = (const float*)d_in[1];   // [128,128,1]
    const float* W   = (const float*)d_in[2];   // [128,128]
    const float* a   = (const float*)d_in[3];   // [256,128]
    float* out = (float*)d_out;

    cudaFuncSetAttribute(attn_fused, cudaFuncAttributeMaxDynamicSharedMemorySize,
                         ATTN_SMEM_BYTES);

    gemmA<<<80, 512>>>(h, W);

    dim3 g1(80, 2);
    gemmB<<<g1, 512>>>(a);

    dim3 g2(32, NTIME);
    attn_fused<<<g2, 512, ATTN_SMEM_BYTES>>>(adj, out);
}

// round 9
// speedup vs baseline: 1.0293x; 1.0293x over previous
#include <cuda_runtime.h>
#include <cstdint>
#include <cstddef>
#include <cstring>

#define NTIME 20
#define V     128
#define F     128
#define LRELU_ALPHA 0.2f
#define LOG2E 1.4426950408889634f

#define OUT_HP_ELEMS   (NTIME * V * F)
#define ATT_OFF        OUT_HP_ELEMS

__device__ float g_Wh[NTIME * V * F];
__device__ float g_e1[NTIME * V * F];   // scaled by LOG2E
__device__ float g_e2[NTIME * V * F];   // scaled by LOG2E
__device__ float g_C1[F * F];           // (W @ a1) * LOG2E
__device__ float g_C2[F * F];           // (W @ a2) * LOG2E

// ---- packed f32x2 helpers (Blackwell) --------------------------------------
__device__ __forceinline__ float2 addx2(float2 a, float2 b) {
    unsigned long long ua, ub, uc;
    memcpy(&ua, &a, 8); memcpy(&ub, &b, 8);
    asm("add.rn.f32x2 %0, %1, %2;" : "=l"(uc) : "l"(ua), "l"(ub));
    float2 c; memcpy(&c, &uc, 8); return c;
}
__device__ __forceinline__ float2 mulx2(float2 a, float2 b) {
    unsigned long long ua, ub, uc;
    memcpy(&ua, &a, 8); memcpy(&ub, &b, 8);
    asm("mul.rn.f32x2 %0, %1, %2;" : "=l"(uc) : "l"(ua), "l"(ub));
    float2 c; memcpy(&c, &uc, 8); return c;
}
__device__ __forceinline__ float ex2(float x) {
    float r; asm("ex2.approx.f32 %0, %1;" : "=f"(r) : "f"(x)); return r;
}

// ----------------------------------------------------------------------------
// R6-proven gemm tile: 256 threads, MT=16 rows, 8 rows/thread.
// ----------------------------------------------------------------------------
#define MT 16

__device__ __forceinline__ void gemm_tile_256(
    const float* __restrict__ smtile,   // [MT][F]
    const float* __restrict__ M,        // [F][F]
    float* __restrict__ dst, int m0, int tid, float scale)
{
    const int f    = tid & 127;
    const int half = tid >> 7;

    float acc[8] = {0.f,0.f,0.f,0.f,0.f,0.f,0.f,0.f};

#pragma unroll 8
    for (int k4 = 0; k4 < F / 4; k4++) {
        float mv[4];
#pragma unroll
        for (int u = 0; u < 4; u++)
            mv[u] = __ldg(M + (k4 * 4 + u) * F + f);
#pragma unroll
        for (int r = 0; r < 8; r++) {
            const float4 hv = ((const float4*)(smtile + (half * 8 + r) * F))[k4];
            acc[r] = fmaf(hv.x, mv[0], acc[r]);
            acc[r] = fmaf(hv.y, mv[1], acc[r]);
            acc[r] = fmaf(hv.z, mv[2], acc[r]);
            acc[r] = fmaf(hv.w, mv[3], acc[r]);
        }
    }

#pragma unroll
    for (int r = 0; r < 8; r++)
        dst[(size_t)(m0 + half * 8 + r) * F + f] = acc[r] * scale;
}

// ----------------------------------------------------------------------------
// Kernel A: blocks [0,160): Wh = h @ W (R6 config)
//           blocks [160,416): split-K C{1,2} = (W @ a{1,2}) * LOG2E
// prep rides concurrently with the Wh gemm (no serialized launch).
// ----------------------------------------------------------------------------
__global__ void __launch_bounds__(256) gemmA(
    const float* __restrict__ h,
    const float* __restrict__ W,
    const float* __restrict__ a)
{
    __shared__ float smem[MT * F];   // Wh: h tile (8KB); prep: wrow[128]+red[256]

    const int tid = threadIdx.x;

    if (blockIdx.x < 160) {
        const int m0 = blockIdx.x * MT;
        const float4* h4 = (const float4*)(h + (size_t)m0 * F);
        ((float4*)smem)[tid]       = h4[tid];
        ((float4*)smem)[tid + 256] = h4[tid + 256];
        __syncthreads();
        gemm_tile_256(smem, W, g_Wh, m0, tid, 1.0f);
    } else {
        float* wrow = smem;          // [128]
        float* red  = smem + 128;    // [256]
        const int idx  = blockIdx.x - 160;
        const int m    = idx & 127;
        const int half = idx >> 7;
        const int f    = tid & 127;
        const int kh   = tid >> 7;   // 0..1

        if (tid < 128)
            wrow[tid] = __ldg(W + (size_t)m * F + tid);
        __syncthreads();

        const float* ap = a + (size_t)half * F * F + kh * 64 * F + f;
        float acc = 0.0f;
#pragma unroll
        for (int u = 0; u < 64; u++)
            acc = fmaf(wrow[kh * 64 + u], __ldg(ap + u * F), acc);

        red[tid] = acc;
        __syncthreads();

        if (kh == 0) {
            float* dst = half ? g_C2 : g_C1;
            dst[(size_t)m * F + f] = (red[f] + red[f + 128]) * LOG2E;
        }
    }
}

// ----------------------------------------------------------------------------
// Kernel B: e{1,2} = h @ C{1,2}. grid = (160, 2), R6 config.
// ----------------------------------------------------------------------------
__global__ void __launch_bounds__(256) gemmB(const float* __restrict__ h)
{
    __shared__ float hs[MT * F];
    const int tid = threadIdx.x;
    const int m0  = blockIdx.x * MT;
    const int by  = blockIdx.y;

    const float4* h4 = (const float4*)(h + (size_t)m0 * F);
    ((float4*)hs)[tid]       = h4[tid];
    ((float4*)hs)[tid + 256] = h4[tid + 256];
    __syncthreads();

    gemm_tile_256(hs, by ? g_C2 : g_C1, by ? g_e2 : g_e1, m0, tid, 1.0f);
}

// ----------------------------------------------------------------------------
// Kernel C: attention (R7 j-split, unchanged). Two warps per (i, f-half), each
// owning 64 j's; partial (s,num) exchanged via smem; 10240 total warps.
// Block = 512 threads, grid = 32 x 20 = 640, smem 72KB, 3 CTA/SM.
// ----------------------------------------------------------------------------
#define FH  64
#define IPB 8
#define ATTN_SMEM_BYTES ((2 * V * FH + 16 * 32 * 4) * (int)sizeof(float))

__global__ void __launch_bounds__(512, 3) attn_fused(
    const float* __restrict__ adj,
    float* __restrict__ out)
{
    extern __shared__ float sm[];
    float*  e2s = sm;                        // [V][FH]  (scaled by LOG2E)
    float*  whs = sm + V * FH;               // [V][FH]
    float4* red = (float4*)(sm + 2 * V * FH);

    const int t    = blockIdx.y;
    const int bx   = blockIdx.x;      // 0..31
    const int fh   = bx & 1;
    const int ig   = bx >> 1;         // 0..15
    const int tid  = threadIdx.x;
    const int lane = tid & 31;
    const int w    = tid >> 5;        // warp 0..15
    const int il   = w >> 1;          // local i 0..7
    const int jh   = w & 1;           // j-half
    const int i    = ig * IPB + il;
    const int f2   = fh * FH + lane * 2;

    uint32_t bits[2];
    {
        const float* arow = adj + (size_t)i * V + jh * 64;
        bits[0] = __ballot_sync(0xFFFFFFFFu, arow[lane]      > 0.0f);
        bits[1] = __ballot_sync(0xFFFFFFFFu, arow[32 + lane] > 0.0f);
    }

    {
        const float* e2g = g_e2 + (size_t)t * V * F + fh * FH;
        const float* whg = g_Wh + (size_t)t * V * F + fh * FH;
#pragma unroll
        for (int u = 0; u < 4; u++) {
            const int idx = tid + u * 512;
            const int j = idx >> 4, c = idx & 15;
            ((float4*)e2s)[idx] = *(const float4*)(e2g + j * F + c * 4);
            ((float4*)whs)[idx] = *(const float4*)(whg + j * F + c * 4);
        }
    }

    const float2 e1v = *(const float2*)(g_e1 + ((size_t)t * V + i) * F + f2);
    const float2 A2  = make_float2(LRELU_ALPHA, LRELU_ALPHA);
    __syncthreads();

    const float* e2l = e2s + jh * 64 * FH + lane * 2;
    const float* whl = whs + jh * 64 * FH + lane * 2;

    float s0 = 0.0f, s1 = 0.0f, n0 = 0.0f, n1 = 0.0f;
#pragma unroll
    for (int ww = 0; ww < 2; ww++) {
        const uint32_t bw = bits[ww];
        const float* e2w = e2l + ww * 32 * FH;
        const float* whw = whl + ww * 32 * FH;
#pragma unroll
        for (int b = 0; b < 32; b++) {
            if (bw & (1u << b)) {
                const float2 e2v = *(const float2*)(e2w + b * FH);
                const float2 v   = addx2(e1v, e2v);
                const float2 av  = mulx2(v, A2);
                const float  m0v = fmaxf(v.x, av.x);
                const float  m1v = fmaxf(v.y, av.y);
                const float  p0  = ex2(m0v);
                const float  p1  = ex2(m1v);
                const float2 wv  = *(const float2*)(whw + b * FH);
                s0 += p0;  s1 += p1;
                n0 = fmaf(p0, wv.x, n0);
                n1 = fmaf(p1, wv.y, n1);
            }
        }
    }

    red[w * 32 + lane] = make_float4(s0, s1, n0, n1);
    __syncthreads();
    {
        const float4 o = red[(w ^ 1) * 32 + lane];
        s0 += o.x; s1 += o.y; n0 += o.z; n1 += o.w;
    }

    const float r0 = 1.0f / s0;
    const float r1 = 1.0f / s1;

    if (jh == 0) {
        const float hp0 = n0 * r0;
        const float hp1 = n1 * r1;
        float2 o;
        o.x = (hp0 > 0.0f) ? hp0 : expm1f(hp0);
        o.y = (hp1 > 0.0f) ? hp1 : expm1f(hp1);
        *(float2*)(out + ((size_t)t * V + i) * F + f2) = o;
    }

    float* ab = out + ATT_OFF + (((size_t)t * V + i) * V + jh * 64) * F + f2;
#pragma unroll
    for (int ww = 0; ww < 2; ww++) {
        const uint32_t bw = bits[ww];
        const float* e2w = e2l + ww * 32 * FH;
        float* abw = ab + (size_t)ww * 32 * F;
#pragma unroll
        for (int b = 0; b < 32; b++) {
            float2 pv;
            if (bw & (1u << b)) {
                const float2 e2v = *(const float2*)(e2w + b * FH);
                const float2 v   = addx2(e1v, e2v);
                const float2 av  = mulx2(v, A2);
                const float  m0v = fmaxf(v.x, av.x);
                const float  m1v = fmaxf(v.y, av.y);
                pv.x = ex2(m0v) * r0;
                pv.y = ex2(m1v) * r1;
            } else {
                pv.x = 0.0f; pv.y = 0.0f;
            }
            __stcs((float2*)(abw + b * F), pv);
        }
    }
}

// ----------------------------------------------------------------------------
extern "C" void kernel_launch(void* const* d_in, const int* in_sizes, int n_in,
                              void* d_out, int out_size)
{
    const float* h   = (const float*)d_in[0];   // [2560,128]
    const float* adj = (const float*)d_in[1];   // [128,128,1]
    const float* W   = (const float*)d_in[2];   // [128,128]
    const float* a   = (const float*)d_in[3];   // [256,128]
    float* out = (float*)d_out;

    cudaFuncSetAttribute(attn_fused, cudaFuncAttributeMaxDynamicSharedMemorySize,
                         ATTN_SMEM_BYTES);

    gemmA<<<416, 256>>>(h, W, a);

    dim3 g1(160, 2);
    gemmB<<<g1, 256>>>(h);

    dim3 g2(32, NTIME);
    attn_fused<<<g2, 512, ATTN_SMEM_BYTES>>>(adj, out);
}